// round 1
// baseline (speedup 1.0000x reference)
#include <cuda_runtime.h>
#include <math.h>

// Problem constants (fixed by the dataset)
#define BSZ   64
#define LSEQ  100
#define LP1   101
#define DIM   64
#define NCOL  (BSZ * LP1)   // 6464
#define NROW  (BSZ * LSEQ)  // 6400
#define NEG10K (-10000.0f)

// Tiling
#define CCH   37            // column chunks (37*16 = 592 CTAs = 4 exact waves on 148 SMs)
#define GRPB  4             // batches per CTA
#define RPC   (GRPB * LSEQ) // 400 active rows per CTA
#define TPB   416           // 13 warps

// Scratch (__device__ globals; no allocations allowed)
__device__ int   g_nv;
__device__ int   g_colid[NCOL];
__device__ int   g_itemid[NCOL];
__device__ float g_addterm[NCOL];          // -log(pop[item]) per compacted column
__device__ float g_keep[BSZ * NCOL];       // per-(batch, compacted col): -log(pop) or -inf
__device__ float g_tgt[NROW];              // masked target logit per row
__device__ float g_partS[CCH * NROW];      // per-chunk partial exp-sums

// ---------------------------------------------------------------------------
// 1) Compact valid columns (col_valid depends only on log_mask; deterministic
//    single-block prefix scan). Also gathers item id and -log(pop) per slot.
// ---------------------------------------------------------------------------
__global__ void compact_kernel(const int* __restrict__ log_mask,
                               const int* __restrict__ items,
                               const float* __restrict__ pop) {
    __shared__ int s[1024];
    int t = threadIdx.x;
    int offset = 0;
    for (int base = 0; base < NCOL; base += 1024) {
        int k = base + t;
        int flag = 0;
        if (k < NCOL) {
            int i = k / LP1, pos = k % LP1;
            flag = (pos == LSEQ) ? 1 : (log_mask[i * LSEQ + pos] != 0);
        }
        s[t] = flag;
        __syncthreads();
        // Hillis-Steele inclusive scan
        for (int d = 1; d < 1024; d <<= 1) {
            int v = (t >= d) ? s[t - d] : 0;
            __syncthreads();
            s[t] += v;
            __syncthreads();
        }
        if (flag) {
            int slot = offset + s[t] - 1;
            g_colid[slot] = k;
            int id = items[k];
            g_itemid[slot] = id;
            g_addterm[slot] = -logf(pop[id]);
        }
        int tot = s[1023];
        __syncthreads();
        offset += tot;
    }
    if (t == 0) g_nv = offset;
}

// ---------------------------------------------------------------------------
// 2) Per-batch dup mask over compacted columns: keep = dup ? -inf : -log(pop).
//    dup(i,k) = item(k) appears among batch i's 101 sequence items.
// ---------------------------------------------------------------------------
__global__ void dup_kernel(const int* __restrict__ items) {
    __shared__ int ids[LP1];
    int i = blockIdx.x;
    int t = threadIdx.x;
    if (t < LP1) ids[t] = items[i * LP1 + t];
    __syncthreads();
    int nv = g_nv;
    const float NINF = __int_as_float(0xff800000);
    for (int kv = t; kv < nv; kv += blockDim.x) {
        int id = g_itemid[kv];
        bool dup = false;
        #pragma unroll 4
        for (int j = 0; j < LP1; j++) dup |= (id == ids[j]);
        g_keep[i * NCOL + kv] = dup ? NINF : g_addterm[kv];
    }
}

// ---------------------------------------------------------------------------
// 3) Target logits: v_tgt(r) = col_valid(tgt) ? dot(prec[r], emb[tgt]) - log(pop)
//                                             : -10000   (dup mask never applies)
//    One warp per row.
// ---------------------------------------------------------------------------
__global__ void target_kernel(const float* __restrict__ prec,
                              const float* __restrict__ embs,
                              const float* __restrict__ pop,
                              const int* __restrict__ items,
                              const int* __restrict__ log_mask) {
    int warp = threadIdx.x >> 5;
    int lane = threadIdx.x & 31;
    int r = blockIdx.x * 4 + warp;
    if (r >= NROW) return;
    int i = r / LSEQ, j = r % LSEQ;
    int pos = j + 1;
    int valid = (pos == LSEQ) ? 1 : (log_mask[i * LSEQ + pos] != 0);
    int tc = i * LP1 + pos;
    float out = NEG10K;
    if (valid) {
        float s = prec[r * DIM + lane]      * embs[tc * DIM + lane]
                + prec[r * DIM + lane + 32] * embs[tc * DIM + lane + 32];
        #pragma unroll
        for (int o = 16; o > 0; o >>= 1) s += __shfl_down_sync(0xffffffffu, s, o);
        out = s - logf(pop[items[tc]]);
    }
    if (lane == 0) g_tgt[r] = out;
}

// ---------------------------------------------------------------------------
// 4) Main fused matmul + exp + row-sum over compacted columns.
//    CTA = (column chunk, group of 4 batches). Each thread owns one row:
//    prec row in 64 registers; embedding columns staged in SMEM and read via
//    uniform (broadcast) LDS.128; per-thread running exp-sum.
// ---------------------------------------------------------------------------
__global__ __launch_bounds__(TPB, 1)
void main_kernel(const float* __restrict__ prec, const float* __restrict__ embs) {
    __shared__ float embT[64 * 64];      // 64 columns x 64 dims, 16 KB
    __shared__ float keepT[GRPB * 64];   // per-local-batch keep-add terms
    int nv = g_nv;
    int chunk = blockIdx.x;
    int grp = blockIdx.y;
    int cw = (nv + CCH - 1) / CCH;
    int k0 = chunk * cw;
    int k1 = min(nv, k0 + cw);
    int t = threadIdx.x;
    bool act = t < RPC;
    int row = grp * RPC + t;
    int bl = t / LSEQ;                   // local batch 0..3 (only used when act)

    float4 p[16];
    if (act) {
        const float4* pr = (const float4*)(prec + row * DIM);
        #pragma unroll
        for (int q = 0; q < 16; q++) p[q] = pr[q];
    }

    float ssum = 0.f;
    float4* embT4 = (float4*)embT;
    const float4* embs4 = (const float4*)embs;

    for (int kk = k0; kk < k1; kk += 64) {
        int kmax = min(64, k1 - kk);
        // stage embedding columns (gather via compacted indices)
        for (int idx = t; idx < kmax * 16; idx += TPB) {
            int kloc = idx >> 4;
            int col = g_colid[kk + kloc];
            embT4[idx] = embs4[col * 16 + (idx & 15)];
        }
        // stage keep-add terms for the 4 batches of this group
        for (int idx = t; idx < GRPB * 64; idx += TPB) {
            int ib = idx >> 6, kloc = idx & 63;
            if (kloc < kmax)
                keepT[idx] = g_keep[(grp * GRPB + ib) * NCOL + kk + kloc];
        }
        __syncthreads();
        if (act) {
            #pragma unroll 4
            for (int k = 0; k < kmax; k++) {
                const float4* e = (const float4*)&embT[k * 64];
                float d0 = 0.f, d1 = 0.f, d2 = 0.f, d3 = 0.f;
                #pragma unroll
                for (int q = 0; q < 16; q++) {
                    float4 ev = e[q];
                    d0 = fmaf(p[q].x, ev.x, d0);
                    d1 = fmaf(p[q].y, ev.y, d1);
                    d2 = fmaf(p[q].z, ev.z, d2);
                    d3 = fmaf(p[q].w, ev.w, d3);
                }
                float v = (d0 + d1) + (d2 + d3) + keepT[bl * 64 + k];
                ssum += __expf(v);   // -inf -> 0 for dup-masked columns
            }
        }
        __syncthreads();
    }
    if (act) g_partS[chunk * NROW + row] = ssum;
}

// ---------------------------------------------------------------------------
// 5) Final reduce: S_r = sum of chunk partials + exp(v_tgt); nll = log(S)-v_tgt;
//    weighted mean over log_mask!=0 rows in double precision. Single block,
//    deterministic.
// ---------------------------------------------------------------------------
__global__ void reduce_kernel(const int* __restrict__ log_mask,
                              float* __restrict__ out) {
    __shared__ double sn[1024];
    __shared__ double sd[1024];
    int t = threadIdx.x;
    double num = 0.0, den = 0.0;
    for (int r = t; r < NROW; r += 1024) {
        float S = 0.f;
        #pragma unroll 4
        for (int c = 0; c < CCH; c++) S += g_partS[c * NROW + r];
        float tv = g_tgt[r];
        S += __expf(tv);             // exp(-10000) underflows to 0, as in ref
        float nll = (S > 0.f) ? (logf(S) - tv) : logf((float)NCOL);
        if (log_mask[r] != 0) { num += (double)nll; den += 1.0; }
    }
    sn[t] = num; sd[t] = den;
    __syncthreads();
    for (int o = 512; o > 0; o >>= 1) {
        if (t < o) { sn[t] += sn[t + o]; sd[t] += sd[t + o]; }
        __syncthreads();
    }
    if (t == 0) out[0] = (float)(sn[0] / sd[0]);
}

// ---------------------------------------------------------------------------
extern "C" void kernel_launch(void* const* d_in, const int* in_sizes, int n_in,
                              void* d_out, int out_size) {
    const float* prec  = (const float*)d_in[0];  // [6400, 64]
    const float* embs  = (const float*)d_in[1];  // [6464, 64]
    const float* pop   = (const float*)d_in[2];  // [100001]
    const int*   items = (const int*)d_in[3];    // [6464]
    const int*   lmask = (const int*)d_in[4];    // [64, 100]
    float* out = (float*)d_out;

    compact_kernel<<<1, 1024>>>(lmask, items, pop);
    dup_kernel<<<BSZ, 256>>>(items);
    target_kernel<<<(NROW + 3) / 4, 128>>>(prec, embs, pop, items, lmask);
    main_kernel<<<dim3(CCH, 16), TPB>>>(prec, embs);
    reduce_kernel<<<1, 1024>>>(lmask, out);
}

// round 3
// speedup vs baseline: 2.6503x; 2.6503x over previous
#include <cuda_runtime.h>
#include <math.h>
#include <stdint.h>

// Problem constants
#define BSZ   64
#define LSEQ  100
#define LP1   101
#define DIM   64
#define NCOL  (BSZ * LP1)   // 6464
#define NROW  (BSZ * LSEQ)  // 6400
#define NCOLP 6592          // padded compacted-col bound (multiple of 128 headroom)
#define NEG10K (-10000.0f)

#define NCH   6             // N chunk-slices (grid.y)
#define NSL   (NCH * 2)     // partS slices (2 warp-halves per CTA)
#define STR   68            // smem row stride in floats (bank-conflict-free)
#define TILEB (128 * STR * 4)

// ---------------- scratch (__device__ globals; no allocs) ----------------
__device__ int    g_nv;
__device__ int    g_colid[NCOL];
__device__ int    g_itemid[NCOL];
__device__ float  g_addterm[NCOL];
__device__ float  g_keep[BSZ * NCOLP];   // -log(pop) or -inf per (batch, padded compacted col)
__device__ float  g_Amat[NROW * DIM];    // tf32-rounded prec
__device__ float  g_Bmat[NCOLP * DIM];   // tf32-rounded, compacted, padded embeddings
__device__ float  g_tgt[NROW];
__device__ float  g_partS[NSL * NROW];
__device__ double g_rn[64];
__device__ double g_rd[64];

// ---------------- PTX helpers ----------------
__device__ __forceinline__ uint32_t smem_u32(const void* p) {
    uint32_t a;
    asm("{ .reg .u64 t; cvta.to.shared.u64 t, %1; cvt.u32.u64 %0, t; }" : "=r"(a) : "l"(p));
    return a;
}
__device__ __forceinline__ uint32_t f2tf(float x) {  // fp32 -> tf32 round-to-nearest
    uint32_t u;
    asm("cvt.rna.tf32.f32 %0, %1;" : "=r"(u) : "f"(x));
    return u;
}
__device__ __forceinline__ void cp16(uint32_t dst, const void* src) {
    asm volatile("cp.async.ca.shared.global [%0], [%1], 16;" :: "r"(dst), "l"(src) : "memory");
}
#define CP_COMMIT()  asm volatile("cp.async.commit_group;" ::: "memory")
#define CP_WAIT0()   asm volatile("cp.async.wait_group 0;" ::: "memory")
#define CP_WAIT1()   asm volatile("cp.async.wait_group 1;" ::: "memory")

__device__ __forceinline__ void mma8(float* c, const uint32_t* a, uint32_t b0, uint32_t b1) {
    asm volatile("mma.sync.aligned.m16n8k8.row.col.f32.tf32.tf32.f32 "
        "{%0,%1,%2,%3}, {%4,%5,%6,%7}, {%8,%9}, {%0,%1,%2,%3};"
        : "+f"(c[0]), "+f"(c[1]), "+f"(c[2]), "+f"(c[3])
        : "r"(a[0]), "r"(a[1]), "r"(a[2]), "r"(a[3]), "r"(b0), "r"(b1));
}

// ---------------------------------------------------------------------------
// 1) Compact valid columns — ballot-based single-block scan.
// ---------------------------------------------------------------------------
__global__ void compact_kernel(const int* __restrict__ log_mask,
                               const int* __restrict__ items,
                               const float* __restrict__ pop) {
    __shared__ int wsum[32];
    __shared__ int wbase[32];
    __shared__ int s_tot;
    __shared__ int s_off;
    int t = threadIdx.x, lane = t & 31, w = t >> 5;
    if (t == 0) s_off = 0;
    __syncthreads();
    for (int base = 0; base < NCOL; base += 1024) {
        int k = base + t;
        int flag = 0;
        if (k < NCOL) {
            int i = k / LP1, pos = k % LP1;
            flag = (pos == LSEQ) ? 1 : (log_mask[i * LSEQ + pos] != 0);
        }
        unsigned bal = __ballot_sync(0xffffffffu, flag);
        if (lane == 0) wsum[w] = __popc(bal);
        __syncthreads();
        if (w == 0) {
            int v = wsum[lane];
            int s = v;
            #pragma unroll
            for (int o = 1; o < 32; o <<= 1) {
                int u = __shfl_up_sync(0xffffffffu, s, o);
                if (lane >= o) s += u;
            }
            wbase[lane] = s - v;
            if (lane == 31) s_tot = s;
        }
        __syncthreads();
        if (flag) {
            int slot = s_off + wbase[w] + __popc(bal & ((1u << lane) - 1u));
            g_colid[slot] = k;
            int id = items[k];
            g_itemid[slot] = id;
            g_addterm[slot] = -logf(pop[id]);
        }
        __syncthreads();
        if (t == 0) s_off += s_tot;
        __syncthreads();
    }
    if (t == 0) g_nv = s_off;
}

// ---------------------------------------------------------------------------
// 2) Per-batch dup mask over compacted (padded) columns
// ---------------------------------------------------------------------------
__global__ void dup_kernel(const int* __restrict__ items) {
    __shared__ int ids[LP1];
    int i = blockIdx.x;
    int t = threadIdx.x;
    if (t < LP1) ids[t] = items[i * LP1 + t];
    __syncthreads();
    int nv = g_nv;
    int nvp = (nv + 127) & ~127;
    const float NINF = __int_as_float(0xff800000);
    for (int kv = t; kv < nvp; kv += blockDim.x) {
        float out = NINF;
        if (kv < nv) {
            int id = g_itemid[kv];
            bool dup = false;
            #pragma unroll 4
            for (int j = 0; j < LP1; j++) dup |= (id == ids[j]);
            out = dup ? NINF : g_addterm[kv];
        }
        g_keep[i * NCOLP + kv] = out;
    }
}

// ---------------------------------------------------------------------------
// 3) Prep: tf32-round A; gather+round+compact B (zeros past nv)
// ---------------------------------------------------------------------------
__global__ void prep_kernel(const float* __restrict__ prec,
                            const float* __restrict__ embs) {
    int idx = blockIdx.x * 256 + threadIdx.x;
    const int nA = NROW * 16;
    const float4* p4 = (const float4*)prec;
    const float4* e4 = (const float4*)embs;
    if (idx < nA) {
        float4 v = p4[idx];
        uint4 u = make_uint4(f2tf(v.x), f2tf(v.y), f2tf(v.z), f2tf(v.w));
        ((uint4*)g_Amat)[idx] = u;
    } else {
        int j = idx - nA;
        if (j < NCOLP * 16) {
            int c = j >> 4, q = j & 15;
            uint4 u = make_uint4(0u, 0u, 0u, 0u);
            if (c < g_nv) {
                float4 v = e4[g_colid[c] * 16 + q];
                u = make_uint4(f2tf(v.x), f2tf(v.y), f2tf(v.z), f2tf(v.w));
            }
            ((uint4*)g_Bmat)[j] = u;
        }
    }
}

// ---------------------------------------------------------------------------
// 4) Target logits (fp32 exact — one warp per row)
// ---------------------------------------------------------------------------
__global__ void target_kernel(const float* __restrict__ prec,
                              const float* __restrict__ embs,
                              const float* __restrict__ pop,
                              const int* __restrict__ items,
                              const int* __restrict__ log_mask) {
    int warp = threadIdx.x >> 5;
    int lane = threadIdx.x & 31;
    int r = blockIdx.x * 4 + warp;
    if (r >= NROW) return;
    int i = r / LSEQ, j = r % LSEQ;
    int pos = j + 1;
    int valid = (pos == LSEQ) ? 1 : (log_mask[i * LSEQ + pos] != 0);
    int tc = i * LP1 + pos;
    float out = NEG10K;
    if (valid) {
        float s = prec[r * DIM + lane] * embs[tc * DIM + lane]
                + prec[r * DIM + lane + 32] * embs[tc * DIM + lane + 32];
        #pragma unroll
        for (int o = 16; o > 0; o >>= 1) s += __shfl_down_sync(0xffffffffu, s, o);
        out = s - logf(pop[items[tc]]);
    }
    if (lane == 0) g_tgt[r] = out;
}

// ---------------------------------------------------------------------------
// 5) Main: tf32 mma.sync GEMM + fused exp row-sum epilogue.
//    CTA = (M-tile 128 rows, N chunk-slice). 256 threads = 8 warps:
//    warps 0-3 cover rows, cols [0,64); warps 4-7 cover rows, cols [64,128).
//    B tiles (128 cols x 64 dims) double-buffered via cp.async.
// ---------------------------------------------------------------------------
#define SMEM_BYTES (3 * TILEB + 2 * 1536)

__global__ __launch_bounds__(256, 1)
void main_kernel() {
    extern __shared__ float sm[];
    float* As = sm;                         // [128][STR]
    float* Bs0 = sm + 128 * STR;
    float* Bs1 = sm + 2 * 128 * STR;
    float* Ks0 = sm + 3 * 128 * STR;        // [3][128]
    float* Ks1 = Ks0 + 384;
    const uint32_t su = smem_u32(sm);
    const uint32_t Bu[2] = {su + TILEB, su + 2 * TILEB};
    const uint32_t Ku[2] = {su + 3 * TILEB, su + 3 * TILEB + 1536};
    float* Bsb[2] = {Bs0, Bs1};
    float* Ksb[2] = {Ks0, Ks1};

    const int t = threadIdx.x;
    const int w = t >> 5, lane = t & 31;
    const int g = lane >> 2, tig = lane & 3;
    const int m0 = blockIdx.x * 128;
    const int ch = blockIdx.y;
    const int nv = g_nv;
    const int T = (nv + 127) >> 7;          // 128-col tiles
    const int ntiles = (T > ch) ? ((T - 1 - ch) / NCH + 1) : 0;
    const int bfirst = m0 / LSEQ;
    const int whalf = w >> 2;
    const int wm = (w & 3) * 32;
    const int slice = ch * 2 + whalf;

    float rs[4] = {0.f, 0.f, 0.f, 0.f};
    // rows owned by this thread: m0+wm+mt*16+g(+8)
    int bl[4];
    #pragma unroll
    for (int mt = 0; mt < 2; mt++) {
        #pragma unroll
        for (int h = 0; h < 2; h++) {
            int row = m0 + wm + mt * 16 + g + h * 8;
            bl[mt * 2 + h] = row / LSEQ - bfirst;
        }
    }

    if (ntiles == 0) {
        if (tig == 0) {
            #pragma unroll
            for (int mt = 0; mt < 2; mt++)
                #pragma unroll
                for (int h = 0; h < 2; h++)
                    g_partS[slice * NROW + m0 + wm + mt * 16 + g + h * 8] = 0.f;
        }
        return;
    }

    // ---- stage A + tile 0 (group 0), tile 1 (group 1) ----
    auto stageB = [&](int tile, int buf) {
        int kb = tile * 128;
        const float* Bg = g_Bmat + kb * 64;
        for (int i = t; i < 2048; i += 256) {
            int r = i >> 4, q = i & 15;
            cp16(Bu[buf] + (r * STR + q * 4) * 4, Bg + r * 64 + q * 4);
        }
        for (int i = t; i < 96; i += 256) {
            int b = i >> 5, q = i & 31;
            int bg = min(bfirst + b, BSZ - 1);
            cp16(Ku[buf] + (b * 128 + q * 4) * 4, g_keep + bg * NCOLP + kb + q * 4);
        }
    };

    {
        const float* Ag = g_Amat + m0 * 64;
        for (int i = t; i < 2048; i += 256) {
            int r = i >> 4, q = i & 15;
            cp16(su + (r * STR + q * 4) * 4, Ag + r * 64 + q * 4);
        }
        stageB(ch, 0);
        CP_COMMIT();
        if (ntiles > 1) { stageB(ch + NCH, 1); CP_COMMIT(); }
        if (ntiles > 1) CP_WAIT1(); else CP_WAIT0();
        __syncthreads();
    }

    // ---- load A fragments (reused across all tiles) ----
    uint32_t a[2][8][4];
    {
        const float* Ar = As + (wm + g) * STR + tig;
        #pragma unroll
        for (int mt = 0; mt < 2; mt++) {
            #pragma unroll
            for (int kt = 0; kt < 8; kt++) {
                const float* p = Ar + mt * 16 * STR + kt * 8;
                a[mt][kt][0] = __float_as_uint(p[0]);
                a[mt][kt][1] = __float_as_uint(p[8 * STR]);
                a[mt][kt][2] = __float_as_uint(p[4]);
                a[mt][kt][3] = __float_as_uint(p[8 * STR + 4]);
            }
        }
    }

    for (int ti = 0; ti < ntiles; ti++) {
        int buf = ti & 1;
        const float* B = Bsb[buf];
        const float* KP = Ksb[buf];
        const int cb = whalf * 64;

        #pragma unroll
        for (int cc = 0; cc < 4; cc++) {    // four 16-col chunks
            const int C = cb + cc * 16;
            float c[2][2][4];
            #pragma unroll
            for (int mt = 0; mt < 2; mt++)
                #pragma unroll
                for (int nt = 0; nt < 2; nt++)
                    #pragma unroll
                    for (int q = 0; q < 4; q++) c[mt][nt][q] = 0.f;

            #pragma unroll
            for (int kt = 0; kt < 8; kt++) {
                const float* b0p = B + (C + g) * STR + kt * 8 + tig;
                const float* b1p = b0p + 8 * STR;
                uint32_t b00 = __float_as_uint(b0p[0]);
                uint32_t b01 = __float_as_uint(b0p[4]);
                uint32_t b10 = __float_as_uint(b1p[0]);
                uint32_t b11 = __float_as_uint(b1p[4]);
                mma8(c[0][0], a[0][kt], b00, b01);
                mma8(c[0][1], a[0][kt], b10, b11);
                mma8(c[1][0], a[1][kt], b00, b01);
                mma8(c[1][1], a[1][kt], b10, b11);
            }

            #pragma unroll
            for (int mt = 0; mt < 2; mt++) {
                #pragma unroll
                for (int nt = 0; nt < 2; nt++) {
                    int col = C + nt * 8 + 2 * tig;
                    float k00 = KP[bl[mt * 2 + 0] * 128 + col];
                    float k01 = KP[bl[mt * 2 + 0] * 128 + col + 1];
                    float k10 = KP[bl[mt * 2 + 1] * 128 + col];
                    float k11 = KP[bl[mt * 2 + 1] * 128 + col + 1];
                    rs[mt * 2 + 0] += __expf(c[mt][nt][0] + k00)
                                    + __expf(c[mt][nt][1] + k01);
                    rs[mt * 2 + 1] += __expf(c[mt][nt][2] + k10)
                                    + __expf(c[mt][nt][3] + k11);
                }
            }
        }

        __syncthreads();                    // everyone done reading buf
        if (ti + 2 < ntiles) { stageB(ch + (ti + 2) * NCH, buf); CP_COMMIT(); }
        if (ti + 1 < ntiles) {
            if (ti + 2 < ntiles) CP_WAIT1(); else CP_WAIT0();
            __syncthreads();
        }
    }

    // reduce partial sums over the 4 lanes (tig) of each row group
    #pragma unroll
    for (int q = 0; q < 4; q++) {
        rs[q] += __shfl_xor_sync(0xffffffffu, rs[q], 1);
        rs[q] += __shfl_xor_sync(0xffffffffu, rs[q], 2);
    }
    if (tig == 0) {
        #pragma unroll
        for (int mt = 0; mt < 2; mt++)
            #pragma unroll
            for (int h = 0; h < 2; h++)
                g_partS[slice * NROW + m0 + wm + mt * 16 + g + h * 8] = rs[mt * 2 + h];
    }
}

// ---------------------------------------------------------------------------
// 6) Two-stage deterministic reduction
// ---------------------------------------------------------------------------
__global__ void reduce1_kernel(const int* __restrict__ log_mask) {
    __shared__ double sn[128];
    __shared__ double sd[128];
    int t = threadIdx.x;
    int r = blockIdx.x * 128 + t;
    float S = 0.f;
    #pragma unroll
    for (int c = 0; c < NSL; c++) S += g_partS[c * NROW + r];
    float tv = g_tgt[r];
    S += __expf(tv);
    float nll = (S > 0.f) ? (logf(S) - tv) : logf((float)NCOL);
    bool wv = (log_mask[r] != 0);
    sn[t] = wv ? (double)nll : 0.0;
    sd[t] = wv ? 1.0 : 0.0;
    __syncthreads();
    for (int o = 64; o > 0; o >>= 1) {
        if (t < o) { sn[t] += sn[t + o]; sd[t] += sd[t + o]; }
        __syncthreads();
    }
    if (t == 0) { g_rn[blockIdx.x] = sn[0]; g_rd[blockIdx.x] = sd[0]; }
}

__global__ void reduce2_kernel(float* __restrict__ out) {
    __shared__ double sn[64];
    __shared__ double sd[64];
    int t = threadIdx.x;
    sn[t] = (t < 50) ? g_rn[t] : 0.0;
    sd[t] = (t < 50) ? g_rd[t] : 0.0;
    __syncthreads();
    for (int o = 32; o > 0; o >>= 1) {
        if (t < o) { sn[t] += sn[t + o]; sd[t] += sd[t + o]; }
        __syncthreads();
    }
    if (t == 0) out[0] = (float)(sn[0] / sd[0]);
}

// ---------------------------------------------------------------------------
extern "C" void kernel_launch(void* const* d_in, const int* in_sizes, int n_in,
                              void* d_out, int out_size) {
    const float* prec  = (const float*)d_in[0];  // [6400, 64]
    const float* embs  = (const float*)d_in[1];  // [6464, 64]
    const float* pop   = (const float*)d_in[2];  // [100001]
    const int*   items = (const int*)d_in[3];    // [6464]
    const int*   lmask = (const int*)d_in[4];    // [64, 100]
    float* out = (float*)d_out;

    cudaFuncSetAttribute(main_kernel, cudaFuncAttributeMaxDynamicSharedMemorySize,
                         SMEM_BYTES);

    compact_kernel<<<1, 1024>>>(lmask, items, pop);
    dup_kernel<<<BSZ, 512>>>(items);
    prep_kernel<<<(NROW * 16 + NCOLP * 16 + 255) / 256, 256>>>(prec, embs);
    target_kernel<<<(NROW + 3) / 4, 128>>>(prec, embs, pop, items, lmask);
    main_kernel<<<dim3(NROW / 128, NCH), 256, SMEM_BYTES>>>();
    reduce1_kernel<<<NROW / 128, 128>>>(lmask);
    reduce2_kernel<<<1, 64>>>(out);
}

// round 4
// speedup vs baseline: 2.6527x; 1.0009x over previous
#include <cuda_runtime.h>
#include <math.h>
#include <stdint.h>

// Problem constants
#define BSZ   64
#define LSEQ  100
#define LP1   101
#define DIM   64
#define NCOL  (BSZ * LP1)   // 6464
#define NROW  (BSZ * LSEQ)  // 6400
#define NCOLP 6592          // padded compacted-col bound (multiple of 128)
#define NEG10K (-10000.0f)
#define LOG2E 1.4426950408889634f

#define NCH   6             // N chunk-slices (grid.y)
#define NSL   (NCH * 2)     // partS slices (2 warp col-halves per CTA)
#define STR   68            // smem row stride in floats (bank-conflict-free)
#define TILEB (128 * STR * 4)

// ---------------- scratch (__device__ globals; no allocs) ----------------
__device__ int    g_nv;
__device__ int    g_colid[NCOL];
__device__ int    g_itemid[NCOL];
__device__ float  g_addterm[NCOL];       // -log2(pop) per compacted column
__device__ float  g_keep[BSZ * NCOLP];   // -log2(pop) or -inf per (batch, padded col)
__device__ float  g_Amat[NROW * DIM];    // tf32(prec * log2e)
__device__ float  g_Bmat[NCOLP * DIM];   // tf32, compacted, zero-padded embeddings
__device__ float  g_tgt[NROW];
__device__ float  g_partS[NSL * NROW];
__device__ double g_rn[64];
__device__ double g_rd[64];

// ---------------- PTX helpers ----------------
__device__ __forceinline__ uint32_t smem_u32(const void* p) {
    uint32_t a;
    asm("{ .reg .u64 t; cvta.to.shared.u64 t, %1; cvt.u32.u64 %0, t; }" : "=r"(a) : "l"(p));
    return a;
}
__device__ __forceinline__ uint32_t f2tf(float x) {  // fp32 -> tf32 round-to-nearest
    uint32_t u;
    asm("cvt.rna.tf32.f32 %0, %1;" : "=r"(u) : "f"(x));
    return u;
}
__device__ __forceinline__ float ex2f(float x) {     // 2^x, -inf -> 0
    float y;
    asm("ex2.approx.f32 %0, %1;" : "=f"(y) : "f"(x));
    return y;
}
__device__ __forceinline__ void cp16(uint32_t dst, const void* src) {
    asm volatile("cp.async.ca.shared.global [%0], [%1], 16;" :: "r"(dst), "l"(src) : "memory");
}
#define CP_COMMIT()  asm volatile("cp.async.commit_group;" ::: "memory")
#define CP_WAIT0()   asm volatile("cp.async.wait_group 0;" ::: "memory")
#define CP_WAIT1()   asm volatile("cp.async.wait_group 1;" ::: "memory")
#define CP_WAIT2()   asm volatile("cp.async.wait_group 2;" ::: "memory")

__device__ __forceinline__ void mma8(float* c, const uint32_t* a, uint32_t b0, uint32_t b1) {
    asm volatile("mma.sync.aligned.m16n8k8.row.col.f32.tf32.tf32.f32 "
        "{%0,%1,%2,%3}, {%4,%5,%6,%7}, {%8,%9}, {%0,%1,%2,%3};"
        : "+f"(c[0]), "+f"(c[1]), "+f"(c[2]), "+f"(c[3])
        : "r"(a[0]), "r"(a[1]), "r"(a[2]), "r"(a[3]), "r"(b0), "r"(b1));
}

// ---------------------------------------------------------------------------
// 1) Compact valid columns — warp-per-2-batches, 2 block syncs total.
//    Column order within and across batches preserved (matches flat k order).
// ---------------------------------------------------------------------------
__global__ void compact_kernel(const int* __restrict__ log_mask,
                               const int* __restrict__ items,
                               const float* __restrict__ pop) {
    __shared__ int cnt[64];
    __shared__ int off[64];
    int t = threadIdx.x, w = t >> 5, lane = t & 31;

    // phase 1: counts
    #pragma unroll
    for (int s = 0; s < 2; s++) {
        int b = 2 * w + s;
        int c = 0;
        #pragma unroll
        for (int ch = 0; ch < 4; ch++) {
            int pos = ch * 32 + lane;
            int flag = 0;
            if (pos <= LSEQ) flag = (pos == LSEQ) ? 1 : (log_mask[b * LSEQ + pos] != 0);
            c += __popc(__ballot_sync(0xffffffffu, flag));
        }
        if (lane == 0) cnt[b] = c;
    }
    __syncthreads();

    // phase 2: exclusive offsets over 64 batch counts (warp 0)
    if (w == 0) {
        int c0 = cnt[2 * lane], c1 = cnt[2 * lane + 1];
        int s = c0 + c1, sc = s;
        #pragma unroll
        for (int o = 1; o < 32; o <<= 1) {
            int u = __shfl_up_sync(0xffffffffu, sc, o);
            if (lane >= o) sc += u;
        }
        int base = sc - s;
        off[2 * lane] = base;
        off[2 * lane + 1] = base + c0;
        if (lane == 31) g_nv = sc;
    }
    __syncthreads();

    // phase 3: scatter
    #pragma unroll
    for (int s = 0; s < 2; s++) {
        int b = 2 * w + s;
        int o = off[b];
        #pragma unroll
        for (int ch = 0; ch < 4; ch++) {
            int pos = ch * 32 + lane;
            int flag = 0;
            if (pos <= LSEQ) flag = (pos == LSEQ) ? 1 : (log_mask[b * LSEQ + pos] != 0);
            unsigned bal = __ballot_sync(0xffffffffu, flag);
            if (flag) {
                int slot = o + __popc(bal & ((1u << lane) - 1u));
                int k = b * LP1 + pos;
                g_colid[slot] = k;
                int id = items[k];
                g_itemid[slot] = id;
                g_addterm[slot] = -log2f(pop[id]);
            }
            o += __popc(bal);
        }
    }
}

// ---------------------------------------------------------------------------
// 2) Fused dup-mask + prep (both depend only on compact; run in parallel).
//    blocks 0..63: per-batch dup mask over padded compacted columns
//    blocks 64.. : tf32-round A (scaled by log2e) and gather+round B
// ---------------------------------------------------------------------------
#define PREP_ELEMS (NROW * 16 + NCOLP * 16)

__global__ void dupprep_kernel(const int* __restrict__ items,
                               const float* __restrict__ prec,
                               const float* __restrict__ embs) {
    if (blockIdx.x < BSZ) {
        __shared__ int ids[LP1];
        int i = blockIdx.x;
        int t = threadIdx.x;
        if (t < LP1) ids[t] = items[i * LP1 + t];
        __syncthreads();
        int nv = g_nv;
        int nvp = (nv + 127) & ~127;
        const float NINF = __int_as_float(0xff800000);
        for (int kv = t; kv < nvp; kv += blockDim.x) {
            float out = NINF;
            if (kv < nv) {
                int id = g_itemid[kv];
                bool dup = false;
                #pragma unroll 4
                for (int j = 0; j < LP1; j++) dup |= (id == ids[j]);
                out = dup ? NINF : g_addterm[kv];
            }
            g_keep[i * NCOLP + kv] = out;
        }
    } else {
        int idx = (blockIdx.x - BSZ) * 512 + threadIdx.x;
        const int nA = NROW * 16;
        const float4* p4 = (const float4*)prec;
        const float4* e4 = (const float4*)embs;
        if (idx < nA) {
            float4 v = p4[idx];
            uint4 u = make_uint4(f2tf(v.x * LOG2E), f2tf(v.y * LOG2E),
                                 f2tf(v.z * LOG2E), f2tf(v.w * LOG2E));
            ((uint4*)g_Amat)[idx] = u;
        } else {
            int j = idx - nA;
            if (j < NCOLP * 16) {
                int c = j >> 4, q = j & 15;
                uint4 u = make_uint4(0u, 0u, 0u, 0u);
                if (c < g_nv) {
                    float4 v = e4[g_colid[c] * 16 + q];
                    u = make_uint4(f2tf(v.x), f2tf(v.y), f2tf(v.z), f2tf(v.w));
                }
                ((uint4*)g_Bmat)[j] = u;
            }
        }
    }
}

// ---------------------------------------------------------------------------
// 3) Target logits (fp32 exact) — 8 threads/row, float4 loads
// ---------------------------------------------------------------------------
__global__ void target_kernel(const float* __restrict__ prec,
                              const float* __restrict__ embs,
                              const float* __restrict__ pop,
                              const int* __restrict__ items,
                              const int* __restrict__ log_mask) {
    int t = threadIdx.x;
    int rloc = t >> 3, sub = t & 7;
    int r = blockIdx.x * 32 + rloc;
    int i = r / LSEQ, j = r - i * LSEQ;
    int pos = j + 1;
    int valid = (pos == LSEQ) ? 1 : (log_mask[i * LSEQ + pos] != 0);
    int tc = i * LP1 + pos;
    const float4* p4 = (const float4*)(prec + r * DIM);
    const float4* e4 = (const float4*)(embs + tc * DIM);
    float4 a0 = p4[sub], b0 = e4[sub], a1 = p4[sub + 8], b1 = e4[sub + 8];
    float s = a0.x * b0.x + a0.y * b0.y + a0.z * b0.z + a0.w * b0.w
            + a1.x * b1.x + a1.y * b1.y + a1.z * b1.z + a1.w * b1.w;
    s += __shfl_down_sync(0xffffffffu, s, 4);
    s += __shfl_down_sync(0xffffffffu, s, 2);
    s += __shfl_down_sync(0xffffffffu, s, 1);
    if (sub == 0) g_tgt[r] = valid ? (s - logf(pop[items[tc]])) : NEG10K;
}

// ---------------------------------------------------------------------------
// 4) Main: tf32 mma.sync GEMM + fused exp2 row-sum epilogue.
//    512 threads = 16 warps; warp tile 16 rows x 64 cols; 3-deep cp.async ring.
// ---------------------------------------------------------------------------
#define SMEM_BYTES (4 * TILEB + 3 * 1536)

__global__ __launch_bounds__(512, 1)
void main_kernel() {
    extern __shared__ float sm[];
    float* As = sm;                          // [128][STR] A tile (staged once)
    const uint32_t su = smem_u32(sm);
    const uint32_t Bu[3] = {su + TILEB, su + 2 * TILEB, su + 3 * TILEB};
    const uint32_t Ku[3] = {su + 4 * TILEB, su + 4 * TILEB + 1536, su + 4 * TILEB + 3072};
    float* Bsb[3] = {sm + 128 * STR, sm + 2 * 128 * STR, sm + 3 * 128 * STR};
    float* Ksb[3] = {sm + 4 * 128 * STR, sm + 4 * 128 * STR + 384, sm + 4 * 128 * STR + 768};

    const int t = threadIdx.x;
    const int w = t >> 5, lane = t & 31;
    const int g = lane >> 2, tig = lane & 3;
    const int m0 = blockIdx.x * 128;
    const int ch = blockIdx.y;
    const int nv = g_nv;
    const int T = (nv + 127) >> 7;
    const int ntiles = (T > ch) ? ((T - ch + NCH - 1) / NCH) : 0;
    const int bfirst = m0 / LSEQ;
    const int whalf = w & 1;
    const int wm = (w >> 1) * 16;
    const int cb = whalf * 64;
    const int slice = ch * 2 + whalf;

    const int row0 = m0 + wm + g;
    const int bl0 = row0 / LSEQ - bfirst;
    const int bl1 = (row0 + 8) / LSEQ - bfirst;
    float rs0 = 0.f, rs1 = 0.f;

    if (ntiles == 0) {
        if (tig == 0) {
            g_partS[slice * NROW + row0] = 0.f;
            g_partS[slice * NROW + row0 + 8] = 0.f;
        }
        return;
    }

    auto stageB = [&](int tile, int buf) {
        int kb = tile * 128;
        const float* Bg = g_Bmat + kb * 64;
        #pragma unroll
        for (int i = 0; i < 4; i++) {
            int idx = t + i * 512;
            int r = idx >> 4, q = idx & 15;
            cp16(Bu[buf] + (r * STR + q * 4) * 4, Bg + r * 64 + q * 4);
        }
        if (t < 96) {
            int b = t >> 5, q = t & 31;
            int bg = min(bfirst + b, BSZ - 1);
            cp16(Ku[buf] + (b * 128 + q * 4) * 4, g_keep + bg * NCOLP + kb + q * 4);
        }
    };

    // prologue: stage A with tile 0, then tiles 1, 2
    {
        const float* Ag = g_Amat + m0 * 64;
        #pragma unroll
        for (int i = 0; i < 4; i++) {
            int idx = t + i * 512;
            int r = idx >> 4, q = idx & 15;
            cp16(su + (r * STR + q * 4) * 4, Ag + r * 64 + q * 4);
        }
    }
    stageB(ch, 0);
    CP_COMMIT();
    int committed = 1;
    if (ntiles > 1) { stageB(ch + NCH, 1); CP_COMMIT(); committed = 2; }
    if (ntiles > 2) { stageB(ch + 2 * NCH, 2); CP_COMMIT(); committed = 3; }

    uint32_t a[8][4];

    for (int ti = 0; ti < ntiles; ti++) {
        int rem = committed - ti - 1;
        if (rem >= 2) CP_WAIT2(); else if (rem == 1) CP_WAIT1(); else CP_WAIT0();
        __syncthreads();

        if (ti == 0) {
            const float* Ar = As + (wm + g) * STR + tig;
            #pragma unroll
            for (int kt = 0; kt < 8; kt++) {
                const float* p = Ar + kt * 8;
                a[kt][0] = __float_as_uint(p[0]);
                a[kt][1] = __float_as_uint(p[8 * STR]);
                a[kt][2] = __float_as_uint(p[4]);
                a[kt][3] = __float_as_uint(p[8 * STR + 4]);
            }
        }

        int buf = ti - (ti / 3) * 3;
        const float* B = Bsb[buf];
        const float* KP = Ksb[buf];

        #pragma unroll
        for (int cc = 0; cc < 4; cc++) {
            const int C = cb + cc * 16;
            float c0[4] = {0.f, 0.f, 0.f, 0.f};
            float c1[4] = {0.f, 0.f, 0.f, 0.f};
            #pragma unroll
            for (int kt = 0; kt < 8; kt++) {
                const float* b0p = B + (C + g) * STR + kt * 8 + tig;
                const float* b1p = b0p + 8 * STR;
                uint32_t b00 = __float_as_uint(b0p[0]);
                uint32_t b01 = __float_as_uint(b0p[4]);
                uint32_t b10 = __float_as_uint(b1p[0]);
                uint32_t b11 = __float_as_uint(b1p[4]);
                mma8(c0, a[kt], b00, b01);
                mma8(c1, a[kt], b10, b11);
            }
            #pragma unroll
            for (int nt = 0; nt < 2; nt++) {
                const float* cr = nt ? c1 : c0;
                int col = C + nt * 8 + 2 * tig;
                float2 k0 = *(const float2*)(KP + bl0 * 128 + col);
                float2 k1 = *(const float2*)(KP + bl1 * 128 + col);
                rs0 += ex2f(cr[0] + k0.x) + ex2f(cr[1] + k0.y);
                rs1 += ex2f(cr[2] + k1.x) + ex2f(cr[3] + k1.y);
            }
        }

        __syncthreads();
        if (ti + 3 < ntiles) { stageB(ch + (ti + 3) * NCH, buf); CP_COMMIT(); committed++; }
    }

    // reduce over the 4 tig lanes of each row group
    rs0 += __shfl_xor_sync(0xffffffffu, rs0, 1);
    rs0 += __shfl_xor_sync(0xffffffffu, rs0, 2);
    rs1 += __shfl_xor_sync(0xffffffffu, rs1, 1);
    rs1 += __shfl_xor_sync(0xffffffffu, rs1, 2);
    if (tig == 0) {
        g_partS[slice * NROW + row0] = rs0;
        g_partS[slice * NROW + row0 + 8] = rs1;
    }
}

// ---------------------------------------------------------------------------
// 5) Two-stage deterministic reduction
// ---------------------------------------------------------------------------
__global__ void reduce1_kernel(const int* __restrict__ log_mask) {
    __shared__ double sn[128];
    __shared__ double sd[128];
    int t = threadIdx.x;
    int r = blockIdx.x * 128 + t;
    float S = 0.f;
    #pragma unroll
    for (int c = 0; c < NSL; c++) S += g_partS[c * NROW + r];
    float tv = g_tgt[r];
    S += __expf(tv);
    float nll = (S > 0.f) ? (logf(S) - tv) : logf((float)NCOL);
    bool wv = (log_mask[r] != 0);
    sn[t] = wv ? (double)nll : 0.0;
    sd[t] = wv ? 1.0 : 0.0;
    __syncthreads();
    for (int o = 64; o > 0; o >>= 1) {
        if (t < o) { sn[t] += sn[t + o]; sd[t] += sd[t + o]; }
        __syncthreads();
    }
    if (t == 0) { g_rn[blockIdx.x] = sn[0]; g_rd[blockIdx.x] = sd[0]; }
}

__global__ void reduce2_kernel(float* __restrict__ out) {
    __shared__ double sn[64];
    __shared__ double sd[64];
    int t = threadIdx.x;
    sn[t] = (t < 50) ? g_rn[t] : 0.0;
    sd[t] = (t < 50) ? g_rd[t] : 0.0;
    __syncthreads();
    for (int o = 32; o > 0; o >>= 1) {
        if (t < o) { sn[t] += sn[t + o]; sd[t] += sd[t + o]; }
        __syncthreads();
    }
    if (t == 0) out[0] = (float)(sn[0] / sd[0]);
}

// ---------------------------------------------------------------------------
extern "C" void kernel_launch(void* const* d_in, const int* in_sizes, int n_in,
                              void* d_out, int out_size) {
    const float* prec  = (const float*)d_in[0];  // [6400, 64]
    const float* embs  = (const float*)d_in[1];  // [6464, 64]
    const float* pop   = (const float*)d_in[2];  // [100001]
    const int*   items = (const int*)d_in[3];    // [6464]
    const int*   lmask = (const int*)d_in[4];    // [64, 100]
    float* out = (float*)d_out;

    cudaFuncSetAttribute(main_kernel, cudaFuncAttributeMaxDynamicSharedMemorySize,
                         SMEM_BYTES);

    compact_kernel<<<1, 1024>>>(lmask, items, pop);
    dupprep_kernel<<<BSZ + (PREP_ELEMS + 511) / 512, 512>>>(items, prec, embs);
    target_kernel<<<NROW / 32, 256>>>(prec, embs, pop, items, lmask);
    main_kernel<<<dim3(NROW / 128, NCH), 512, SMEM_BYTES>>>();
    reduce1_kernel<<<NROW / 128, 128>>>(lmask);
    reduce2_kernel<<<1, 64>>>(out);
}

// round 5
// speedup vs baseline: 3.0062x; 1.1333x over previous
#include <cuda_runtime.h>
#include <math.h>
#include <stdint.h>

// Problem constants
#define BSZ   64
#define LSEQ  100
#define LP1   101
#define DIM   64
#define NCOL  (BSZ * LP1)   // 6464
#define NROW  (BSZ * LSEQ)  // 6400
#define NCOLP 6656          // padded compacted-col bound (52 * 128)
#define NEG10K (-10000.0f)
#define LOG2E 1.4426950408889634f

#define NCH   6             // N chunk-slices (grid.y)
#define NSL   (NCH * 4)     // partS slices (4 warp col-groups per CTA)
#define TILEF 8192          // floats per 128x64 fragment tile
#define TILEB (TILEF * 4)   // 32 KB

// ---------------- scratch (__device__ globals; no allocs) ----------------
__device__ int    g_nv;
__device__ int    g_colid[NCOL];
__device__ int    g_itemid[NCOL];
__device__ float  g_addterm[NCOL];        // -log2(pop) per compacted column
__device__ float  g_keep[BSZ * NCOLP];    // -log2(pop) or -inf per (batch, padded col)
__device__ float  g_Afrag[NROW * DIM];    // tf32(prec*log2e) in mma-fragment order
__device__ float  g_Bfrag[NCOLP * DIM];   // tf32 compacted embs in mma-fragment order
__device__ float  g_tgt[NROW];
__device__ float  g_partS[NSL * NROW];
__device__ double g_rn[64];
__device__ double g_rd[64];

// ---------------- PTX helpers ----------------
__device__ __forceinline__ uint32_t smem_u32(const void* p) {
    uint32_t a;
    asm("{ .reg .u64 t; cvta.to.shared.u64 t, %1; cvt.u32.u64 %0, t; }" : "=r"(a) : "l"(p));
    return a;
}
__device__ __forceinline__ uint32_t f2tf(float x) {  // fp32 -> tf32 round-to-nearest
    uint32_t u;
    asm("cvt.rna.tf32.f32 %0, %1;" : "=r"(u) : "f"(x));
    return u;
}
__device__ __forceinline__ float ex2f(float x) {     // 2^x, -inf -> 0
    float y;
    asm("ex2.approx.f32 %0, %1;" : "=f"(y) : "f"(x));
    return y;
}
__device__ __forceinline__ void cp16(uint32_t dst, const void* src) {
    asm volatile("cp.async.ca.shared.global [%0], [%1], 16;" :: "r"(dst), "l"(src) : "memory");
}
#define CP_COMMIT()  asm volatile("cp.async.commit_group;" ::: "memory")
#define CP_WAIT0()   asm volatile("cp.async.wait_group 0;" ::: "memory")
#define CP_WAIT1()   asm volatile("cp.async.wait_group 1;" ::: "memory")
#define CP_WAIT2()   asm volatile("cp.async.wait_group 2;" ::: "memory")

__device__ __forceinline__ void mma8(float* c, const uint32_t* a, uint32_t b0, uint32_t b1) {
    asm volatile("mma.sync.aligned.m16n8k8.row.col.f32.tf32.tf32.f32 "
        "{%0,%1,%2,%3}, {%4,%5,%6,%7}, {%8,%9}, {%0,%1,%2,%3};"
        : "+f"(c[0]), "+f"(c[1]), "+f"(c[2]), "+f"(c[3])
        : "r"(a[0]), "r"(a[1]), "r"(a[2]), "r"(a[3]), "r"(b0), "r"(b1));
}

// ---------------------------------------------------------------------------
// 1) Compact valid columns — warp-per-2-batches, 2 block syncs total.
// ---------------------------------------------------------------------------
__global__ void compact_kernel(const int* __restrict__ log_mask,
                               const int* __restrict__ items,
                               const float* __restrict__ pop) {
    __shared__ int cnt[64];
    __shared__ int off[64];
    int t = threadIdx.x, w = t >> 5, lane = t & 31;

    #pragma unroll
    for (int s = 0; s < 2; s++) {
        int b = 2 * w + s;
        int c = 0;
        #pragma unroll
        for (int ch = 0; ch < 4; ch++) {
            int pos = ch * 32 + lane;
            int flag = 0;
            if (pos <= LSEQ) flag = (pos == LSEQ) ? 1 : (log_mask[b * LSEQ + pos] != 0);
            c += __popc(__ballot_sync(0xffffffffu, flag));
        }
        if (lane == 0) cnt[b] = c;
    }
    __syncthreads();

    if (w == 0) {
        int c0 = cnt[2 * lane], c1 = cnt[2 * lane + 1];
        int s = c0 + c1, sc = s;
        #pragma unroll
        for (int o = 1; o < 32; o <<= 1) {
            int u = __shfl_up_sync(0xffffffffu, sc, o);
            if (lane >= o) sc += u;
        }
        int base = sc - s;
        off[2 * lane] = base;
        off[2 * lane + 1] = base + c0;
        if (lane == 31) g_nv = sc;
    }
    __syncthreads();

    #pragma unroll
    for (int s = 0; s < 2; s++) {
        int b = 2 * w + s;
        int o = off[b];
        #pragma unroll
        for (int ch = 0; ch < 4; ch++) {
            int pos = ch * 32 + lane;
            int flag = 0;
            if (pos <= LSEQ) flag = (pos == LSEQ) ? 1 : (log_mask[b * LSEQ + pos] != 0);
            unsigned bal = __ballot_sync(0xffffffffu, flag);
            if (flag) {
                int slot = o + __popc(bal & ((1u << lane) - 1u));
                int k = b * LP1 + pos;
                g_colid[slot] = k;
                int id = items[k];
                g_itemid[slot] = id;
                g_addterm[slot] = -log2f(pop[id]);
            }
            o += __popc(bal);
        }
    }
}

// ---------------------------------------------------------------------------
// 2) Fused dup-mask + fragment-prep + target (all depend only on compact).
//    blocks [0,64): per-batch dup mask
//    blocks [64,264): A fragments (tf32, scaled by log2e)
//    blocks [264,472): B fragments (tf32, compacted gather)
//    blocks [472,572): exact fp32 target logits (8 threads/row)
// ---------------------------------------------------------------------------
#define AB_BLK  (NROW * 16 / 512)    // 200
#define BB_BLK  (NCOLP * 16 / 512)   // 208
#define TG_BLK  (NROW / 64)          // 100
#define FUSE_BLOCKS (BSZ + AB_BLK + BB_BLK + TG_BLK)

__global__ void dupprep_kernel(const int* __restrict__ items,
                               const float* __restrict__ prec,
                               const float* __restrict__ embs,
                               const float* __restrict__ pop,
                               const int* __restrict__ log_mask) {
    int blk = blockIdx.x;
    int t = threadIdx.x;
    if (blk < BSZ) {
        __shared__ int ids[LP1];
        int i = blk;
        if (t < LP1) ids[t] = items[i * LP1 + t];
        __syncthreads();
        int nv = g_nv;
        int nvp = (nv + 127) & ~127;
        const float NINF = __int_as_float(0xff800000);
        for (int kv = t; kv < nvp; kv += 512) {
            float out = NINF;
            if (kv < nv) {
                int id = g_itemid[kv];
                bool dup = false;
                #pragma unroll 4
                for (int j = 0; j < LP1; j++) dup |= (id == ids[j]);
                out = dup ? NINF : g_addterm[kv];
            }
            g_keep[i * NCOLP + kv] = out;
        }
    } else if (blk < BSZ + AB_BLK) {
        // A fragments: idx -> (mt128, rg, mt01, kt, lane); 4 floats per thread
        int iA = (blk - BSZ) * 512 + t;
        int lane = iA & 31;
        int kt = (iA >> 5) & 7;
        int mt01 = (iA >> 8) & 1;
        int rg = (iA >> 9) & 3;
        int mt128 = iA >> 11;
        int g = lane >> 2, tig = lane & 3;
        int r0 = mt128 * 128 + rg * 32 + mt01 * 16 + g;
        int k0 = kt * 8 + tig;
        float4 u;
        u.x = prec[r0 * DIM + k0] * LOG2E;           // a0: row g,   k
        u.y = prec[(r0 + 8) * DIM + k0] * LOG2E;     // a1: row g+8, k
        u.z = prec[r0 * DIM + k0 + 4] * LOG2E;       // a2: row g,   k+4
        u.w = prec[(r0 + 8) * DIM + k0 + 4] * LOG2E; // a3: row g+8, k+4
        uint4 v = make_uint4(f2tf(u.x), f2tf(u.y), f2tf(u.z), f2tf(u.w));
        ((uint4*)g_Afrag)[iA] = v;
    } else if (blk < BSZ + AB_BLK + BB_BLK) {
        // B fragments: idx -> (ktile, cc, kt, lane)
        int iB = (blk - BSZ - AB_BLK) * 512 + t;
        int lane = iB & 31;
        int kt = (iB >> 5) & 7;
        int cc = (iB >> 8) & 7;
        int ktile = iB >> 11;
        int g = lane >> 2, tig = lane & 3;
        int nv = g_nv;
        int c0 = ktile * 128 + cc * 16 + g;
        int c1 = c0 + 8;
        int k0 = kt * 8 + tig;
        uint4 v = make_uint4(0u, 0u, 0u, 0u);
        if (c0 < nv) {
            const float* e = embs + g_colid[c0] * DIM;
            v.x = f2tf(e[k0]);
            v.y = f2tf(e[k0 + 4]);
        }
        if (c1 < nv) {
            const float* e = embs + g_colid[c1] * DIM;
            v.z = f2tf(e[k0]);
            v.w = f2tf(e[k0 + 4]);
        }
        ((uint4*)g_Bfrag)[iB] = v;
    } else {
        // target logits: 8 threads per row, 64 rows per block
        int rloc = t >> 3, sub = t & 7;
        int r = (blk - BSZ - AB_BLK - BB_BLK) * 64 + rloc;
        int i = r / LSEQ, j = r - i * LSEQ;
        int pos = j + 1;
        int valid = (pos == LSEQ) ? 1 : (log_mask[i * LSEQ + pos] != 0);
        int tc = i * LP1 + pos;
        const float4* p4 = (const float4*)(prec + r * DIM);
        const float4* e4 = (const float4*)(embs + tc * DIM);
        float4 a0 = p4[sub], b0 = e4[sub], a1 = p4[sub + 8], b1 = e4[sub + 8];
        float s = a0.x * b0.x + a0.y * b0.y + a0.z * b0.z + a0.w * b0.w
                + a1.x * b1.x + a1.y * b1.y + a1.z * b1.z + a1.w * b1.w;
        s += __shfl_down_sync(0xffffffffu, s, 4);
        s += __shfl_down_sync(0xffffffffu, s, 2);
        s += __shfl_down_sync(0xffffffffu, s, 1);
        if (sub == 0) g_tgt[r] = valid ? (s - logf(pop[items[tc]])) : NEG10K;
    }
}

// ---------------------------------------------------------------------------
// 3) Main: tf32 mma.sync GEMM, fragment-layout LDS.128, fused exp2 row-sums.
//    512 threads = 16 warps; warp tile 32 rows x 32 cols; 3-deep cp.async ring.
// ---------------------------------------------------------------------------
#define SMEM_BYTES (4 * TILEB + 3 * 1536)

__global__ __launch_bounds__(512, 1)
void main_kernel() {
    extern __shared__ float sm[];
    float* As = sm;
    float* Bsb[3] = {sm + TILEF, sm + 2 * TILEF, sm + 3 * TILEF};
    float* Ksb[3] = {sm + 4 * TILEF, sm + 4 * TILEF + 384, sm + 4 * TILEF + 768};
    const uint32_t su = smem_u32(sm);
    const uint32_t Bu[3] = {su + TILEB, su + 2 * TILEB, su + 3 * TILEB};
    const uint32_t Ku[3] = {su + 4 * TILEB, su + 4 * TILEB + 1536, su + 4 * TILEB + 3072};

    const int t = threadIdx.x;
    const int w = t >> 5, lane = t & 31;
    const int g = lane >> 2, tig = lane & 3;
    const int rg = w >> 2;                   // row group 0..3 (32 rows each)
    const int wcol = w & 3;                  // col group 0..3 (32 cols each)
    const int m0 = blockIdx.x * 128;
    const int ch = blockIdx.y;
    const int nv = g_nv;
    const int T = (nv + 127) >> 7;
    const int ntiles = (T > ch) ? ((T - ch + NCH - 1) / NCH) : 0;
    const int bfirst = m0 / LSEQ;
    const int slice = ch * 4 + wcol;

    // rows owned: m0 + rg*32 + mt*16 + g + h*8
    int bl[2][2];
    #pragma unroll
    for (int mt = 0; mt < 2; mt++)
        #pragma unroll
        for (int h = 0; h < 2; h++)
            bl[mt][h] = (m0 + rg * 32 + mt * 16 + g + h * 8) / LSEQ - bfirst;

    float rs[4] = {0.f, 0.f, 0.f, 0.f};

    if (ntiles == 0) {
        if (tig == 0) {
            #pragma unroll
            for (int mt = 0; mt < 2; mt++)
                #pragma unroll
                for (int h = 0; h < 2; h++)
                    g_partS[slice * NROW + m0 + rg * 32 + mt * 16 + g + h * 8] = 0.f;
        }
        return;
    }

    auto stageB = [&](int tile, int buf) {
        const float* Bg = g_Bfrag + (size_t)tile * TILEF;
        #pragma unroll
        for (int i = 0; i < 4; i++) {
            int idx = t + i * 512;
            cp16(Bu[buf] + idx * 16, Bg + idx * 4);
        }
        if (t < 96) {
            int b = t >> 5, q = t & 31;
            int bg = min(bfirst + b, BSZ - 1);
            cp16(Ku[buf] + (b * 128 + q * 4) * 4, g_keep + (size_t)bg * NCOLP + tile * 128 + q * 4);
        }
    };

    // prologue: stage A + up to 3 B tiles
    {
        const float* Ag = g_Afrag + (size_t)m0 * DIM;
        #pragma unroll
        for (int i = 0; i < 4; i++) {
            int idx = t + i * 512;
            cp16(su + idx * 16, Ag + idx * 4);
        }
    }
    stageB(ch, 0);
    CP_COMMIT();
    int committed = 1;
    if (ntiles > 1) { stageB(ch + NCH, 1); CP_COMMIT(); committed = 2; }
    if (ntiles > 2) { stageB(ch + 2 * NCH, 2); CP_COMMIT(); committed = 3; }

    uint32_t a[2][8][4];

    for (int ti = 0; ti < ntiles; ti++) {
        int rem = committed - ti - 1;
        if (rem >= 2) CP_WAIT2(); else if (rem == 1) CP_WAIT1(); else CP_WAIT0();
        __syncthreads();

        if (ti == 0) {
            // A fragments: 16x LDS.128, fragment-native layout
            #pragma unroll
            for (int mt = 0; mt < 2; mt++)
                #pragma unroll
                for (int kt = 0; kt < 8; kt++) {
                    float4 v = *(const float4*)(As + (((rg * 2 + mt) * 8 + kt) * 32 + lane) * 4);
                    a[mt][kt][0] = __float_as_uint(v.x);
                    a[mt][kt][1] = __float_as_uint(v.y);
                    a[mt][kt][2] = __float_as_uint(v.z);
                    a[mt][kt][3] = __float_as_uint(v.w);
                }
        }

        int buf = ti - (ti / 3) * 3;
        const float* B = Bsb[buf];
        const float* KP = Ksb[buf];

        #pragma unroll
        for (int cc2 = 0; cc2 < 2; cc2++) {
            const int cc = wcol * 2 + cc2;
            const float4* bp = (const float4*)(B + cc * 1024) + lane;
            float c[2][2][4];
            #pragma unroll
            for (int mt = 0; mt < 2; mt++)
                #pragma unroll
                for (int nt = 0; nt < 2; nt++)
                    #pragma unroll
                    for (int q = 0; q < 4; q++) c[mt][nt][q] = 0.f;

            #pragma unroll
            for (int kt = 0; kt < 8; kt++) {
                float4 b = bp[kt * 32];
                uint32_t bx = __float_as_uint(b.x), by = __float_as_uint(b.y);
                uint32_t bz = __float_as_uint(b.z), bw_ = __float_as_uint(b.w);
                mma8(c[0][0], a[0][kt], bx, by);
                mma8(c[0][1], a[0][kt], bz, bw_);
                mma8(c[1][0], a[1][kt], bx, by);
                mma8(c[1][1], a[1][kt], bz, bw_);
            }

            const int C = cc * 16;
            #pragma unroll
            for (int mt = 0; mt < 2; mt++) {
                #pragma unroll
                for (int nt = 0; nt < 2; nt++) {
                    int col = C + nt * 8 + 2 * tig;
                    float2 k0 = *(const float2*)(KP + bl[mt][0] * 128 + col);
                    float2 k1 = *(const float2*)(KP + bl[mt][1] * 128 + col);
                    rs[mt * 2 + 0] += ex2f(c[mt][nt][0] + k0.x) + ex2f(c[mt][nt][1] + k0.y);
                    rs[mt * 2 + 1] += ex2f(c[mt][nt][2] + k1.x) + ex2f(c[mt][nt][3] + k1.y);
                }
            }
        }

        __syncthreads();
        if (ti + 3 < ntiles) { stageB(ch + (ti + 3) * NCH, buf); CP_COMMIT(); committed++; }
    }

    // reduce over the 4 tig lanes of each row
    #pragma unroll
    for (int q = 0; q < 4; q++) {
        rs[q] += __shfl_xor_sync(0xffffffffu, rs[q], 1);
        rs[q] += __shfl_xor_sync(0xffffffffu, rs[q], 2);
    }
    if (tig == 0) {
        #pragma unroll
        for (int mt = 0; mt < 2; mt++)
            #pragma unroll
            for (int h = 0; h < 2; h++)
                g_partS[slice * NROW + m0 + rg * 32 + mt * 16 + g + h * 8] = rs[mt * 2 + h];
    }
}

// ---------------------------------------------------------------------------
// 4) Two-stage deterministic reduction
// ---------------------------------------------------------------------------
__global__ void reduce1_kernel(const int* __restrict__ log_mask) {
    __shared__ double sn[128];
    __shared__ double sd[128];
    int t = threadIdx.x;
    int r = blockIdx.x * 128 + t;
    float S = 0.f;
    #pragma unroll
    for (int c = 0; c < NSL; c++) S += g_partS[c * NROW + r];
    float tv = g_tgt[r];
    S += __expf(tv);
    float nll = (S > 0.f) ? (logf(S) - tv) : logf((float)NCOL);
    bool wv = (log_mask[r] != 0);
    sn[t] = wv ? (double)nll : 0.0;
    sd[t] = wv ? 1.0 : 0.0;
    __syncthreads();
    for (int o = 64; o > 0; o >>= 1) {
        if (t < o) { sn[t] += sn[t + o]; sd[t] += sd[t + o]; }
        __syncthreads();
    }
    if (t == 0) { g_rn[blockIdx.x] = sn[0]; g_rd[blockIdx.x] = sd[0]; }
}

__global__ void reduce2_kernel(float* __restrict__ out) {
    __shared__ double sn[64];
    __shared__ double sd[64];
    int t = threadIdx.x;
    sn[t] = (t < 50) ? g_rn[t] : 0.0;
    sd[t] = (t < 50) ? g_rd[t] : 0.0;
    __syncthreads();
    for (int o = 32; o > 0; o >>= 1) {
        if (t < o) { sn[t] += sn[t + o]; sd[t] += sd[t + o]; }
        __syncthreads();
    }
    if (t == 0) out[0] = (float)(sn[0] / sd[0]);
}

// ---------------------------------------------------------------------------
extern "C" void kernel_launch(void* const* d_in, const int* in_sizes, int n_in,
                              void* d_out, int out_size) {
    const float* prec  = (const float*)d_in[0];  // [6400, 64]
    const float* embs  = (const float*)d_in[1];  // [6464, 64]
    const float* pop   = (const float*)d_in[2];  // [100001]
    const int*   items = (const int*)d_in[3];    // [6464]
    const int*   lmask = (const int*)d_in[4];    // [64, 100]
    float* out = (float*)d_out;

    cudaFuncSetAttribute(main_kernel, cudaFuncAttributeMaxDynamicSharedMemorySize,
                         SMEM_BYTES);

    compact_kernel<<<1, 1024>>>(lmask, items, pop);
    dupprep_kernel<<<FUSE_BLOCKS, 512>>>(items, prec, embs, pop, lmask);
    main_kernel<<<dim3(NROW / 128, NCH), 512, SMEM_BYTES>>>();
    reduce1_kernel<<<NROW / 128, 128>>>(lmask);
    reduce2_kernel<<<1, 64>>>(out);
}